// round 6
// baseline (speedup 1.0000x reference)
#include <cuda_runtime.h>
#include <cstdint>

// Problem: out[N,N] = diag(ics_mask - params * r_mask), N = 12288.
// Pure HBM-store-bound: 604 MB of output, ~all zeros.
// One float4 store per thread; diagonal hit-test in 32-bit int math
// (N^2 = 150,994,944 < 2^31, so element indices fit in uint32).

static constexpr unsigned N = 12288u;
static constexpr unsigned N4 = (N * N) / 4u;   // 37,748,736 float4 stores

__global__ void __launch_bounds__(256) diag_fill_kernel(
    float4* __restrict__ out4,
    const float* __restrict__ params,
    const int*   __restrict__ r_mask,
    const int*   __restrict__ ics_mask)
{
    unsigned t = blockIdx.x * blockDim.x + threadIdx.x;   // < N4 exactly
    unsigned j = t * 4u;                                   // first element index

    float4 v = make_float4(0.f, 0.f, 0.f, 0.f);

    // Diagonal element indices are d = i*(N+1). Since N+1 = 12289 > 4,
    // at most one diagonal element falls in [j, j+4).
    // Smallest candidate i with i*(N+1) >= j is i = ceil(j / (N+1)).
    unsigned i = (j + N) / (N + 1u);          // constant division -> mul+shift
    unsigned d = i * (N + 1u);
    if (i < N && d < j + 4u) {
        float val = (float)ics_mask[i] - params[i] * (float)r_mask[i];
        unsigned off = d - j;                 // 0..3
        if      (off == 0u) v.x = val;
        else if (off == 1u) v.y = val;
        else if (off == 2u) v.z = val;
        else                v.w = val;
    }

    out4[t] = v;
}

extern "C" void kernel_launch(void* const* d_in, const int* in_sizes, int n_in,
                              void* d_out, int out_size)
{
    const float* params   = (const float*)d_in[0];
    const int*   r_mask   = (const int*)  d_in[1];
    const int*   ics_mask = (const int*)  d_in[2];
    float4*      out4     = (float4*)d_out;

    (void)in_sizes; (void)n_in; (void)out_size;

    const unsigned threads = 256;
    const unsigned blocks  = N4 / threads;    // 147,456 — exact, no tail
    diag_fill_kernel<<<blocks, threads>>>(out4, params, r_mask, ics_mask);
}